// round 17
// baseline (speedup 1.0000x reference)
#include <cuda_runtime.h>

// ---------------------------------------------------------------------------
// OmniSuperPointTransformer: gather + pos-MLP (3->32 LN ReLU 32->32) +
// fused segment-mean scatter into superpoints.
//
//  * W2 commutes with segment-sum -> matmul once per superpoint (finalize).
//  * Warp-cooperative points (lane = channel): coalesced gather + scatter.
//  * LN variance as precomputed quadratic form in (x,y,z,1) (10 coeffs).
//  * BATCH-8 SOFTWARE PIPELINE (R16 batch-4 confirmed; this doubles it):
//    red.* asm's "memory" clobber forbids hoisting gathers across REDs, so
//    batches issue 8 named-register LDGs before the batch's first RED ->
//    MLP=8. Full unroll, zero dynamic indexing -> no LMEM.
//  * finalize: 2 superpoints per warp -> shares W2 LDS between two
//    independent FMA chains (issue-bound kernel, -17% instructions, 2x ILP).
//  * pre-centered LayerNorm weights; accumulator [64 interleaved | xyz cnt]
//    = 68 f32/sp (13.6 MB, L2-resident REDs).
// ---------------------------------------------------------------------------

#define N_SP_MAX   50000
#define ACC_STRIDE 68
#define LN_EPS     1e-5f
#define FULLMASK   0xffffffffu

__device__ __align__(16) float g_acc[N_SP_MAX * ACC_STRIDE];
__device__ __align__(16) float g_W1c[96];
__device__ __align__(16) float g_b1c[32];
__device__ __align__(16) float g_Q[12];

__global__ void osp_zero_kernel(int n4) {
    int i = blockIdx.x * blockDim.x + threadIdx.x;
    if (i < n4) reinterpret_cast<float4*>(g_acc)[i] = make_float4(0.f, 0.f, 0.f, 0.f);
}

// Center W1/b1 and build variance quad form:
// var*32 = q0 x^2 + q1 y^2 + q2 z^2 + q3 xy + q4 xz + q5 yz
//        + q6 x + q7 y + q8 z + q9   (cross terms pre-doubled).
__global__ void osp_center_kernel(const float* __restrict__ W1,
                                  const float* __restrict__ b1) {
    __shared__ float m[4];
    __shared__ float cw[128];
    int c = threadIdx.x;               // 32 threads
    if (c < 3) {
        float s = 0.f;
        for (int j = 0; j < 32; j++) s += W1[c * 32 + j];
        m[c] = s * (1.f / 32.f);
    } else if (c == 3) {
        float s = 0.f;
        for (int j = 0; j < 32; j++) s += b1[j];
        m[3] = s * (1.f / 32.f);
    }
    __syncthreads();
    float wx = W1[0 * 32 + c] - m[0];
    float wy = W1[1 * 32 + c] - m[1];
    float wz = W1[2 * 32 + c] - m[2];
    float bb = b1[c] - m[3];
    g_W1c[0 * 32 + c] = wx;  cw[0 * 32 + c] = wx;
    g_W1c[1 * 32 + c] = wy;  cw[1 * 32 + c] = wy;
    g_W1c[2 * 32 + c] = wz;  cw[2 * 32 + c] = wz;
    g_b1c[c]          = bb;  cw[3 * 32 + c] = bb;
    __syncthreads();
    if (c < 10) {
        const int A[10] = {0, 1, 2, 0, 0, 1, 0, 1, 2, 3};
        const int B[10] = {0, 1, 2, 1, 2, 2, 3, 3, 3, 3};
        float s = 0.f;
        for (int j = 0; j < 32; j++) s += cw[A[c] * 32 + j] * cw[B[c] * 32 + j];
        g_Q[c] = (A[c] == B[c]) ? s : 2.f * s;
    }
}

__device__ __forceinline__ void red_add_v2(float* addr, float a, float b) {
    asm volatile("red.global.add.v2.f32 [%0], {%1, %2};"
                 :: "l"(addr), "f"(a), "f"(b) : "memory");
}
__device__ __forceinline__ void red_add_v4(float* addr, float a, float b, float c, float d) {
    asm volatile("red.global.add.v4.f32 [%0], {%1, %2, %3, %4};"
                 :: "l"(addr), "f"(a), "f"(b), "f"(c), "f"(d) : "memory");
}

// ---------------------------------------------------------------------------
// One WARP processes 32 consecutive points; lane = channel.
__global__ __launch_bounds__(256)
void osp_point_kernel(const float* __restrict__ voxel_feats,
                      const float* __restrict__ xyz,
                      const float* __restrict__ gamma,
                      const float* __restrict__ beta,
                      const int*   __restrict__ p2v,
                      const int*   __restrict__ spid,
                      int n_points)
{
    int lane = threadIdx.x & 31;
    int warp = blockIdx.x * (blockDim.x >> 5) + (threadIdx.x >> 5);
    long long pbase = (long long)warp * 32;
    if (pbase >= n_points) return;

    float w1x = g_W1c[lane], w1y = g_W1c[32 + lane], w1z = g_W1c[64 + lane];
    float b1c = g_b1c[lane];
    float gc  = gamma[lane], btc = beta[lane];
    float q0 = g_Q[0], q1 = g_Q[1], q2 = g_Q[2], q3 = g_Q[3], q4 = g_Q[4];
    float q5 = g_Q[5], q6 = g_Q[6], q7 = g_Q[7], q8 = g_Q[8], q9 = g_Q[9];

    bool full = (pbase + 32 <= (long long)n_points);
    int nIter = full ? 32 : (int)((long long)n_points - pbase);

    // coalesced preload: indices + xyz (transposed across 3 lane-registers)
    int pi = (int)pbase + lane;
    int v_l = 0, sp_l = 0;
    float x0 = 0.f, x1 = 0.f, x2 = 0.f;
    if (full) {
        v_l  = p2v[pi];
        sp_l = spid[pi];
        const float* xb = xyz + pbase * 3;
        x0 = xb[lane]; x1 = xb[32 + lane]; x2 = xb[64 + lane];
    } else {
        if (lane < nIter) { v_l = p2v[pi]; sp_l = spid[pi]; }
        int xn = nIter * 3;
        const float* xb = xyz + pbase * 3;
        if (lane      < xn) x0 = xb[lane];
        if (32 + lane < xn) x1 = xb[32 + lane];
        if (64 + lane < xn) x2 = xb[64 + lane];
    }

    // xyz element e (0..95): compile-time selection in the unrolled path.
#define XYZ_ELT(e) __shfl_sync(FULLMASK, ((e) < 32) ? x0 : (((e) < 64) ? x1 : x2), (e) & 31)

#define COMPUTE_R(px, py, pz, rr)                                              \
    {                                                                          \
        float h = fmaf(px, w1x, fmaf(py, w1y, fmaf(pz, w1z, b1c)));            \
        float ta = fmaf(q3, py, fmaf(q4, pz, q6)); ta = fmaf(q0, px, ta);      \
        float tb = fmaf(q1, py, fmaf(q5, pz, q7));                             \
        float tc = fmaf(q2, pz, q8);                                           \
        float v32 = fmaf(px, ta, fmaf(py, tb, fmaf(pz, tc, q9)));              \
        float inv = rsqrtf(fmaf(v32, (1.f / 32.f), LN_EPS));                   \
        rr = fmaxf(fmaf(h * inv, gc, btc), 0.f);                               \
    }

    if (full) {
#pragma unroll
        for (int b = 0; b < 4; b++) {
            const int t0 = 8 * b;

            // ---- phase 1: 8 gathers in flight BEFORE any RED of this batch
#define GTH(i) \
            int   v##i = __shfl_sync(FULLMASK, v_l, t0 + i); \
            float f##i = __ldg(voxel_feats + (size_t)v##i * 32 + lane);
            GTH(0) GTH(1) GTH(2) GTH(3) GTH(4) GTH(5) GTH(6) GTH(7)
#undef GTH

#define SPX(i) \
            int   s##i  = __shfl_sync(FULLMASK, sp_l, t0 + i); \
            float px##i = XYZ_ELT(3 * (t0 + i) + 0); \
            float py##i = XYZ_ELT(3 * (t0 + i) + 1); \
            float pz##i = XYZ_ELT(3 * (t0 + i) + 2);
            SPX(0) SPX(1) SPX(2) SPX(3) SPX(4) SPX(5) SPX(6) SPX(7)
#undef SPX

            // ---- phase 2: MLP + LN(quad form) + ReLU for 8 points
            float r0, r1, r2, r3, r4, r5, r6, r7;
            COMPUTE_R(px0, py0, pz0, r0)
            COMPUTE_R(px1, py1, pz1, r1)
            COMPUTE_R(px2, py2, pz2, r2)
            COMPUTE_R(px3, py3, pz3, r3)
            COMPUTE_R(px4, py4, pz4, r4)
            COMPUTE_R(px5, py5, pz5, r5)
            COMPUTE_R(px6, py6, pz6, r6)
            COMPUTE_R(px7, py7, pz7, r7)

            // ---- phase 3: scatter (coalesced 256B rows)
#define SCT(i) \
            float* a##i = g_acc + (size_t)s##i * ACC_STRIDE; \
            red_add_v2(a##i + 2 * lane, f##i, r##i);
            SCT(0) SCT(1) SCT(2) SCT(3) SCT(4) SCT(5) SCT(6) SCT(7)
#undef SCT
            if (lane == 0) {
                red_add_v4(a0 + 64, px0, py0, pz0, 1.0f);
                red_add_v4(a1 + 64, px1, py1, pz1, 1.0f);
                red_add_v4(a2 + 64, px2, py2, pz2, 1.0f);
                red_add_v4(a3 + 64, px3, py3, pz3, 1.0f);
                red_add_v4(a4 + 64, px4, py4, pz4, 1.0f);
                red_add_v4(a5 + 64, px5, py5, pz5, 1.0f);
                red_add_v4(a6 + 64, px6, py6, pz6, 1.0f);
                red_add_v4(a7 + 64, px7, py7, pz7, 1.0f);
            }
        }
    } else {
        // tail warp (at most one in the grid): simple per-point loop
        for (int t = 0; t < nIter; t++) {
            int v  = __shfl_sync(FULLMASK, v_l,  t);
            int sp = __shfl_sync(FULLMASK, sp_l, t);
            int ix = 3 * t;
            float px = __shfl_sync(FULLMASK, (ix     < 32) ? x0 : ((ix     < 64) ? x1 : x2), ix       & 31);
            float py = __shfl_sync(FULLMASK, (ix + 1 < 32) ? x0 : ((ix + 1 < 64) ? x1 : x2), (ix + 1) & 31);
            float pz = __shfl_sync(FULLMASK, (ix + 2 < 32) ? x0 : ((ix + 2 < 64) ? x1 : x2), (ix + 2) & 31);

            float fc = __ldg(voxel_feats + (size_t)v * 32 + lane);
            float r;
            COMPUTE_R(px, py, pz, r)

            float* base = g_acc + (size_t)sp * ACC_STRIDE;
            red_add_v2(base + 2 * lane, fc, r);
            if (lane == 0) red_add_v4(base + 64, px, py, pz, 1.0f);
        }
    }
#undef COMPUTE_R
#undef XYZ_ELT
}

// ---------------------------------------------------------------------------
// One WARP per TWO superpoints: shares W2 LDS between two independent chains.
__global__ __launch_bounds__(256)
void osp_finalize_kernel(float* __restrict__ out,
                         const float* __restrict__ W2,
                         const float* __restrict__ b2,
                         int S)
{
    __shared__ __align__(16) float sW2[1024];
    for (int t = threadIdx.x; t < 1024; t += blockDim.x) sW2[t] = W2[t];
    __syncthreads();

    int lane = threadIdx.x & 31;
    int spA = (blockIdx.x * (blockDim.x >> 5) + (threadIdx.x >> 5)) * 2;
    if (spA >= S) return;
    bool two = (spA + 1 < S);
    int spB = two ? spA + 1 : spA;

    const float* bA = g_acc + (size_t)spA * ACC_STRIDE;
    const float* bB = g_acc + (size_t)spB * ACC_STRIDE;
    float2 frA = reinterpret_cast<const float2*>(bA)[lane];
    float2 frB = reinterpret_cast<const float2*>(bB)[lane];
    float cntA = bA[67], cntB = bB[67];
    float rinvA = 1.0f / fmaxf(cntA, 1.0f);
    float rinvB = 1.0f / fmaxf(cntB, 1.0f);

    float bias = b2[lane];
    float oA = fmaf(cntA, bias, frA.x);
    float oB = fmaf(cntB, bias, frB.x);
    float rA = frA.y, rB = frB.y;
#pragma unroll
    for (int k = 0; k < 32; k++) {
        float w  = sW2[k * 32 + lane];
        float aA = __shfl_sync(FULLMASK, rA, k);
        float aB = __shfl_sync(FULLMASK, rB, k);
        oA = fmaf(aA, w, oA);
        oB = fmaf(aB, w, oB);
    }

    out[(size_t)spA * 32 + lane] = oA * rinvA;
    if (two) out[(size_t)spB * 32 + lane] = oB * rinvB;
    if (lane < 3) {
        out[(size_t)S * 32 + (size_t)spA * 3 + lane] = bA[64 + lane] * rinvA;
        if (two) out[(size_t)S * 32 + (size_t)spB * 3 + lane] = bB[64 + lane] * rinvB;
    }
}

// ---------------------------------------------------------------------------
extern "C" void kernel_launch(void* const* d_in, const int* in_sizes, int n_in,
                              void* d_out, int out_size)
{
    const float* voxel_feats = (const float*)d_in[0];
    const float* xyz         = (const float*)d_in[1];
    const float* W1          = (const float*)d_in[2];
    const float* b1          = (const float*)d_in[3];
    const float* gamma       = (const float*)d_in[4];
    const float* beta        = (const float*)d_in[5];
    const float* W2          = (const float*)d_in[6];
    const float* b2          = (const float*)d_in[7];
    const int*   p2v         = (const int*)d_in[8];
    const int*   spid        = (const int*)d_in[9];

    int n_points = in_sizes[8];
    int S        = out_size / 35;
    if (S > N_SP_MAX) S = N_SP_MAX;

    int n4 = (S * ACC_STRIDE) / 4;       // 68 % 4 == 0
    osp_zero_kernel<<<(n4 + 255) / 256, 256>>>(n4);
    osp_center_kernel<<<1, 32>>>(W1, b1);

    int warps = (n_points + 31) / 32;            // one warp per 32 points
    int blocks = (warps + 7) / 8;                // 8 warps / 256-thread block
    osp_point_kernel<<<blocks, 256>>>(
        voxel_feats, xyz, gamma, beta, p2v, spid, n_points);

    int fwarps = (S + 1) / 2;                    // one warp per 2 superpoints
    int fblocks = (fwarps + 7) / 8;
    osp_finalize_kernel<<<fblocks, 256>>>((float*)d_out, W2, b2, S);
}